// round 15
// baseline (speedup 1.0000x reference)
#include <cuda_runtime.h>
#include <math.h>

#define BB 2
#define NN 8192

// Ns = {8192,2048,512,128,32}, D = {64,128,256,512,512}
// nsample-1 = {35,23,23,23,23}, kneighbors = {1,4,16,64,256}
// offsets into g_hard/g_pack: {0,16384,20480,21504,21760}

__device__ double   g_ce_sum[6];
__device__ double   g_bl_sum[5];
__device__ unsigned g_bl_cnt[5];
__device__ int      g_hard[21824];
__device__ float4   g_pack[21824];
__device__ float4   g_packQ[BB * NN];   // Morton-sorted stage-0 queries
__device__ int      g_qperm[BB * NN];

struct QSmem {                // quad: 4 queries x 1024 bins (k=256 hard path)
    unsigned hist[4096];
    int      wsum[4][4];
    int      resbin[4], resbelow[4];
    unsigned n[4];
    unsigned cls[4][16];
    unsigned skey[4][256];
    int      sidx[4][256];
};
struct OSmem {                // octo: 8 queries x 512 bins, min-bin sieve
    unsigned hist[4096];
    unsigned char  cbin[8192];
    unsigned short list[3072];
    unsigned ln;
    int      wsum[8][2];
    int      resbin[8], resbelow[8];
    unsigned n[8], nbn[8];
    unsigned cls[8][16];
    unsigned skey[8][128];
    int      sidx[8][128];
    int      nb[8][36];
    float    fd[8][36];
    int      msk[8][36];
};
struct LSmem {                // loss0: center-ball pruned, 8 sorted queries
    unsigned chist[512];
    union { unsigned char cbin[8192]; unsigned qhist[2048]; } u8;  // aliased
    unsigned short list[6144];
    unsigned char  sbin[6144];
    unsigned ln;
    int      wsum[16];
    int      resbin[8], resbelow[8];
    unsigned n[8], nbn[8];
    int      qio[8];
    unsigned skey[8][128];
    int      sidx[8][128];
    int      nb[8][36];
    float    fd[8][36];
    int      msk[8][36];
};
union USmem { QSmem q; OSmem o; LSmem l; };

// ---------------- prep ----------------
__global__ void prep_kernel(const float* __restrict__ x1, const float* __restrict__ x2,
                            const float* __restrict__ x3, const float* __restrict__ x4,
                            const float* __restrict__ x5, const int* __restrict__ labels) {
    int id = blockIdx.x * blockDim.x + threadIdx.x;
    if (id < 6) g_ce_sum[id] = 0.0;
    if (id >= 8 && id < 13) { g_bl_sum[id - 8] = 0.0; g_bl_cnt[id - 8] = 0u; }
    if (id < BB * NN) g_hard[id] = labels[id];
    if (id < 21824) {
        const int offs[6] = {0, 16384, 20480, 21504, 21760, 21824};
        const float* xs[5] = {x1, x2, x3, x4, x5};
        int s = 0;
        while (id >= offs[s + 1]) ++s;
        int r = id - offs[s];
        const float* p = xs[s] + (size_t)r * 3;
        float x = p[0], y = p[1], z = p[2];
        g_pack[id] = make_float4(x, y, z, x * x + y * y + z * z);
    }
}

__device__ __forceinline__ unsigned part3(unsigned x) {
    x &= 1023u;
    x = (x | (x << 16)) & 0x030000FFu;
    x = (x | (x << 8))  & 0x0300F00Fu;
    x = (x | (x << 4))  & 0x030C30C3u;
    x = (x | (x << 2))  & 0x09249249u;
    return x;
}

// ---------------- Morton counting sort of stage-0 queries (one block per b) ----------------
__global__ __launch_bounds__(512) void msort_kernel() {
    __shared__ unsigned hist[4096];
    __shared__ unsigned short scode[8192];
    __shared__ int wsum[16];
    int b = blockIdx.x, tid = threadIdx.x, lane = tid & 31, wid = tid >> 5;
    for (int i = tid; i < 4096; i += 512) hist[i] = 0;
    __syncthreads();
#pragma unroll
    for (int j = 0; j < 16; ++j) {
        int id = tid + j * 512;
        float4 p = g_pack[b * NN + id];
        int cx = min(max((int)((p.x + 4.f) * 2.f), 0), 15);
        int cy = min(max((int)((p.y + 4.f) * 2.f), 0), 15);
        int cz = min(max((int)((p.z + 4.f) * 2.f), 0), 15);
        unsigned code = part3((unsigned)cx) | (part3((unsigned)cy) << 1) | (part3((unsigned)cz) << 2);
        scode[id] = (unsigned short)code;
        atomicAdd(&hist[code], 1u);
    }
    __syncthreads();
    int base = tid * 8, local = 0;
    int pre[8];
#pragma unroll
    for (int r = 0; r < 8; ++r) { pre[r] = local; local += (int)hist[base + r]; }
    int incl = local;
#pragma unroll
    for (int o = 1; o < 32; o <<= 1) {
        int t = __shfl_up_sync(0xFFFFFFFFu, incl, o);
        if (lane >= o) incl += t;
    }
    if (lane == 31) wsum[wid] = incl;
    __syncthreads();
    int woff = 0;
#pragma unroll
    for (int w = 0; w < 16; ++w) woff += (w < wid) ? wsum[w] : 0;
    int excl = woff + incl - local;
    __syncthreads();
#pragma unroll
    for (int r = 0; r < 8; ++r) hist[base + r] = (unsigned)(excl + pre[r]);
    __syncthreads();
#pragma unroll
    for (int j = 0; j < 16; ++j) {
        int id = tid + j * 512;
        unsigned code = scode[id];
        unsigned slot = atomicAdd(&hist[code], 1u);
        g_packQ[b * NN + slot] = g_pack[b * NN + id];
        g_qperm[b * NN + slot] = id;
    }
}

// pinned arithmetic: identical across passes
__device__ __forceinline__ float dist2(float4 q, float4 p) {
    float s = q.z * p.z;
    s = __fmaf_rn(q.y, p.y, s);
    s = __fmaf_rn(q.x, p.x, s);
    return __fmaf_rn(-2.f, s, q.w + p.w);
}

// ---------------- loss0: center-ball pruned body (8 sorted queries) ----------------
__device__ __forceinline__ void loss0n_body(LSmem& sm, int b, int blk,
                                            const float* __restrict__ feat) {
    int tid = threadIdx.x, lane = tid & 31, wid = tid >> 5;
    float4 qc[8];
    if (tid < 8) sm.qio[tid] = g_qperm[b * NN + blk * 8 + tid];
#pragma unroll
    for (int q = 0; q < 8; ++q) qc[q] = g_packQ[b * NN + blk * 8 + q];
    float cx = 0.f, cy = 0.f, cz = 0.f;
#pragma unroll
    for (int q = 0; q < 8; ++q) { cx += qc[q].x; cy += qc[q].y; cz += qc[q].z; }
    cx *= 0.125f; cy *= 0.125f; cz *= 0.125f;
    float4 cen = make_float4(cx, cy, cz, cx * cx + cy * cy + cz * cz);
    float R2 = 0.f;
#pragma unroll
    for (int q = 0; q < 8; ++q) R2 = fmaxf(R2, fmaxf(dist2(cen, qc[q]), 0.f));
    float R = sqrtf(R2);

    sm.chist[tid] = 0;
    if (tid == 0) sm.ln = 0;
    if (tid < 8) { sm.n[tid] = 0; sm.nbn[tid] = 0; }
    __syncthreads();
    const float4* cand = g_pack + b * NN;

    // phase 1: ONE center distance + ONE atomic per candidate
#pragma unroll
    for (int i = 0; i < 16; ++i) {
        int c = tid + i * 512;
        float4 p = cand[c];
        unsigned key = __float_as_uint(fmaxf(dist2(cen, p), 0.f));
        atomicAdd(&sm.chist[(key >> 22) & 511u], 1u);
        int cb = (int)(key >> 20) - 960;
        sm.u8.cbin[c] = (unsigned char)min(max(cb, 0), 255);
    }
    __syncthreads();

    // scan center hist for rank 44 = 36 (k incl self) + 8 (block queries in candidate set)
    {
        int cnt = (int)sm.chist[tid];
        int incl = cnt;
#pragma unroll
        for (int o = 1; o < 32; o <<= 1) {
            int t = __shfl_up_sync(0xFFFFFFFFu, incl, o);
            if (lane >= o) incl += t;
        }
        if (lane == 31) sm.wsum[wid] = incl;
        __syncthreads();
        int woff = 0;
#pragma unroll
        for (int w = 0; w < 16; ++w) woff += (w < wid) ? sm.wsum[w] : 0;
        int excl = woff + incl - cnt;
        if (excl < 44 && 44 <= excl + cnt) sm.resbin[0] = tid;
        __syncthreads();
    }
    float t = __uint_as_float(((unsigned)sm.resbin[0] + 1u) << 22);  // bin upper edge
    float rr = sqrtf(t) + R + R;
    float cutd2 = rr * rr;
    int cut8 = min((int)(__float_as_uint(cutd2) >> 20) - 960 + 1, 255);

    // compact survivors
#pragma unroll
    for (int i = 0; i < 16; ++i) {
        int c = tid + i * 512;
        if ((int)sm.u8.cbin[c] <= cut8) {
            unsigned p = atomicAdd(&sm.ln, 1u);
            if (p < 6144) sm.list[p] = (unsigned short)c;
        }
    }
    __syncthreads();
    int Ln = (int)min(sm.ln, 6144u);
    bool ovf = sm.ln > 6144u;
    ((uint4*)sm.u8.qhist)[tid] = make_uint4(0, 0, 0, 0);
    __syncthreads();

    // phase 2: per-query octave histograms over survivors + per-survivor min-bin
    if (!ovf) {
        for (int j = tid; j < Ln; j += 512) {
            int c = (int)sm.list[j];
            float4 p = cand[c];
            unsigned mb = 255u;
#pragma unroll
            for (int q = 0; q < 8; ++q) {
                unsigned key = __float_as_uint(fmaxf(dist2(qc[q], p), 0.f));
                unsigned bin = (key >> 23) & 255u;
                atomicAdd(&sm.u8.qhist[(q << 8) + bin], 1u);
                mb = min(mb, bin);
            }
            sm.sbin[j] = (unsigned char)mb;
        }
    } else {
#pragma unroll
        for (int i = 0; i < 16; ++i) {
            int c = tid + i * 512;
            float4 p = cand[c];
            unsigned ck = __float_as_uint(fmaxf(dist2(cen, p), 0.f));
            if ((int)(ck >> 20) - 960 > cut8) continue;
#pragma unroll
            for (int q = 0; q < 8; ++q) {
                unsigned key = __float_as_uint(fmaxf(dist2(qc[q], p), 0.f));
                atomicAdd(&sm.u8.qhist[(q << 8) + ((key >> 23) & 255u)], 1u);
            }
        }
    }
    __syncthreads();

    // scan per-query hist for rank 36 (256 bins; 8 groups x 64 threads)
    {
        int g = tid >> 6, t2 = tid & 63, wig = (tid >> 5) & 1;
        int base = (g << 8) + t2 * 4, local = 0;
#pragma unroll
        for (int r = 0; r < 4; ++r) local += (int)sm.u8.qhist[base + r];
        int incl = local;
#pragma unroll
        for (int o = 1; o < 32; o <<= 1) {
            int tt = __shfl_up_sync(0xFFFFFFFFu, incl, o);
            if (lane >= o) incl += tt;
        }
        if (lane == 31) sm.wsum[g * 2 + wig] = incl;
        __syncthreads();
        int woff = wig ? sm.wsum[g * 2] : 0;
        int excl = woff + incl - local;
        if (excl < 36 && 36 <= excl + local) {
            int c2 = excl, bin = t2 * 4;
#pragma unroll
            for (int r = 0; r < 4; ++r) {
                int hh = (int)sm.u8.qhist[base + r];
                if (c2 + hh >= 36) { bin = t2 * 4 + r; break; }
                c2 += hh;
            }
            sm.resbin[g] = bin; sm.resbelow[g] = c2;
        }
        __syncthreads();
    }
    unsigned rb[8]; unsigned rbmax = 0;
#pragma unroll
    for (int q = 0; q < 8; ++q) { rb[q] = (unsigned)sm.resbin[q]; rbmax = max(rbmax, rb[q]); }

    // phase 3: classify survivors (sieved by per-survivor min-bin; drop self at inserts)
    if (!ovf) {
        for (int j = tid; j < Ln; j += 512) {
            if ((unsigned)sm.sbin[j] > rbmax) continue;
            int c = (int)sm.list[j];
            float4 p = cand[c];
#pragma unroll
            for (int q = 0; q < 8; ++q) {
                unsigned key = __float_as_uint(fmaxf(dist2(qc[q], p), 0.f));
                unsigned bin = (key >> 23) & 255u;
                if (bin < rb[q]) {
                    if (c != sm.qio[q]) {
                        unsigned pp = atomicAdd(&sm.nbn[q], 1u);
                        if (pp < 35) sm.nb[q][pp] = c;
                    }
                } else if (bin == rb[q]) {
                    unsigned pp = atomicAdd(&sm.n[q], 1u);
                    if (pp < 128) { sm.skey[q][pp] = key; sm.sidx[q][pp] = c; }
                }
            }
        }
    } else {
#pragma unroll
        for (int i = 0; i < 16; ++i) {
            int c = tid + i * 512;
            float4 p = cand[c];
            unsigned ck = __float_as_uint(fmaxf(dist2(cen, p), 0.f));
            if ((int)(ck >> 20) - 960 > cut8) continue;
#pragma unroll
            for (int q = 0; q < 8; ++q) {
                unsigned key = __float_as_uint(fmaxf(dist2(qc[q], p), 0.f));
                unsigned bin = (key >> 23) & 255u;
                if (bin < rb[q]) {
                    if (c != sm.qio[q]) {
                        unsigned pp = atomicAdd(&sm.nbn[q], 1u);
                        if (pp < 35) sm.nb[q][pp] = c;
                    }
                } else if (bin == rb[q]) {
                    unsigned pp = atomicAdd(&sm.n[q], 1u);
                    if (pp < 128) { sm.skey[q][pp] = key; sm.sidx[q][pp] = c; }
                }
            }
        }
    }
    __syncthreads();

    // exact-rank the rank-bin survivors ((key,idx) lexicographic == top_k tie-break)
    {
        int g = tid >> 6, t2 = tid & 63;
        int n = (int)min(sm.n[g], 128u);
        int need = 36 - sm.resbelow[g];
        for (int j = t2; j < n; j += 64) {
            unsigned kj = sm.skey[g][j]; int ij = sm.sidx[g][j], r = 0;
            for (int m = 0; m < n; ++m) {
                unsigned km = sm.skey[g][m];
                r += (km < kj) || (km == kj && sm.sidx[g][m] < ij);
            }
            if (r < need && ij != sm.qio[g]) {
                unsigned pp = atomicAdd(&sm.nbn[g], 1u);
                if (pp < 35) sm.nb[g][pp] = ij;
            }
        }
    }
    __syncthreads();

    // feature distances (D=64): 2 warps per query
    {
        int g = wid >> 1, w2 = wid & 1;
        int qi = sm.qio[g];
        int myh = g_hard[b * NN + qi];
        const float4* fq = (const float4*)(feat + (size_t)(b * NN + qi) * 64);
        for (int j = w2; j < 35; j += 2) {
            int nbi = sm.nb[g][j];
            const float4* fn = (const float4*)(feat + (size_t)(b * NN + nbi) * 64);
            float ss = 0.f;
            if (lane < 16) {
                float4 a = fq[lane], z = fn[lane];
                float dx = a.x - z.x, dy = a.y - z.y, dz = a.z - z.z, dw = a.w - z.w;
                ss = dx * dx + dy * dy + dz * dz + dw * dw;
            }
#pragma unroll
            for (int o = 16; o; o >>= 1) ss += __shfl_down_sync(0xFFFFFFFFu, ss, o);
            if (lane == 0) {
                sm.fd[g][j] = sqrtf(ss + 1e-6f);
                sm.msk[g][j] = (g_hard[b * NN + nbi] == myh) ? 1 : 0;
            }
        }
    }
    __syncthreads();
    if ((tid & 63) == 0) {
        int g = tid >> 6;
        float dmin = 3.0e38f; int cnt = 0;
        for (int j = 0; j < 35; ++j) { dmin = fminf(dmin, sm.fd[g][j]); cnt += sm.msk[g][j]; }
        if (cnt > 0 && cnt < 35) {
            float pos = 0.f, neg = 0.f;
            for (int j = 0; j < 35; ++j) {
                float e = expf(dmin - sm.fd[g][j]);  // TEMPERATURE = 1
                neg += e;
                if (sm.msk[g][j]) pos += e;
            }
            atomicAdd(&g_bl_sum[0], (double)(-logf(pos / neg + 1e-6f)));
            atomicAdd(&g_bl_cnt[0], 1u);
        }
    }
}

// ---------------- quad body: 4 queries, 1024 bins (k=256 hard path) ----------------
template <int CPT>
__device__ __forceinline__ void quad_body(
        QSmem& sm, int b, int quad, int qoff, int Nq, int k,
        const int* __restrict__ labels) {
    int tid = threadIdx.x, lane = tid & 31;
    int qbase = quad * 4;
    float4 qc[4];
#pragma unroll
    for (int q = 0; q < 4; ++q) qc[q] = g_pack[qoff + b * Nq + qbase + q];
    const float4* cand = g_pack + b * NN;

    uint4* h4 = (uint4*)sm.hist;
    uint4 z4 = make_uint4(0, 0, 0, 0);
    h4[tid] = z4; h4[tid + 512] = z4;
    if (tid < 4) sm.n[tid] = 0;
    if (tid >= 32 && tid < 96) sm.cls[(tid - 32) >> 4][(tid - 32) & 15] = 0;
    __syncthreads();
#pragma unroll
    for (int i = 0; i < CPT; ++i) {
        int c = tid + i * 512;
        float4 p = cand[c];
#pragma unroll
        for (int q = 0; q < 4; ++q) {
            unsigned bin = __float_as_uint(fmaxf(dist2(qc[q], p), 0.f)) >> 21;
            atomicAdd(&sm.hist[(q << 10) + bin], 1u);
        }
    }
    __syncthreads();
    {
        int g = tid >> 7, t = tid & 127, wig = (tid >> 5) & 3;
        const unsigned* h = sm.hist + (g << 10);
        int base = t * 8, local = 0;
#pragma unroll
        for (int r = 0; r < 8; ++r) local += (int)h[base + r];
        int incl = local;
#pragma unroll
        for (int o = 1; o < 32; o <<= 1) {
            int tt = __shfl_up_sync(0xFFFFFFFFu, incl, o);
            if (lane >= o) incl += tt;
        }
        if (lane == 31) sm.wsum[g][wig] = incl;
        __syncthreads();
        int woff = 0;
#pragma unroll
        for (int w = 0; w < 4; ++w) woff += (w < wig) ? sm.wsum[g][w] : 0;
        int excl = woff + incl - local;
        if (excl < k && k <= excl + local) {
            int c2 = excl, bin = base;
#pragma unroll
            for (int r = 0; r < 8; ++r) {
                int hh = (int)h[base + r];
                if (c2 + hh >= k) { bin = base + r; break; }
                c2 += hh;
            }
            sm.resbin[g] = bin; sm.resbelow[g] = c2;
        }
        __syncthreads();
    }
    unsigned rb[4];
#pragma unroll
    for (int q = 0; q < 4; ++q) rb[q] = (unsigned)sm.resbin[q];
#pragma unroll
    for (int i = 0; i < CPT; ++i) {
        int c = tid + i * 512;
        float4 p = cand[c];
#pragma unroll
        for (int q = 0; q < 4; ++q) {
            unsigned key = __float_as_uint(fmaxf(dist2(qc[q], p), 0.f));
            unsigned bin = key >> 21;
            if (bin < rb[q]) {
                atomicAdd(&sm.cls[q][labels[b * NN + c]], 1u);
            } else if (bin == rb[q]) {
                unsigned pp = atomicAdd(&sm.n[q], 1u);
                if (pp < 256) { sm.skey[q][pp] = key; sm.sidx[q][pp] = c; }
            }
        }
    }
    __syncthreads();
    {
        int g = tid >> 7, t = tid & 127;
        int n = (int)min(sm.n[g], 256u);
        int need = k - sm.resbelow[g];
        for (int j = t; j < n; j += 128) {
            unsigned kj = sm.skey[g][j]; int ij = sm.sidx[g][j], r = 0;
            for (int m = 0; m < n; ++m) {
                unsigned km = sm.skey[g][m];
                r += (km < kj) || (km == kj && sm.sidx[g][m] < ij);
            }
            if (r < need) atomicAdd(&sm.cls[g][labels[b * NN + ij]], 1u);
        }
    }
    __syncthreads();
    if ((tid & 127) == 0) {
        int g = tid >> 7;
        int best = 0; unsigned bc = sm.cls[g][0];
#pragma unroll
        for (int cc = 1; cc < 13; ++cc)
            if (sm.cls[g][cc] > bc) { bc = sm.cls[g][cc]; best = cc; }
        g_hard[qoff + b * Nq + qbase + g] = best;
    }
}

// ---------------- octo body: 8 queries, 512 bins, min-bin sieve ----------------
template <int CPT, bool IS_LOSS>
__device__ __forceinline__ void octo_body(
        OSmem& sm, int b, int oct, int qoff, int Nq, int coff, int Ncand,
        int k, int stage, const float* __restrict__ feat, int D,
        const int* __restrict__ labels, bool selfex) {
    int tid = threadIdx.x, lane = tid & 31, wid = tid >> 5;
    int qbase = oct * 8;
    float4 qc[8];
#pragma unroll
    for (int q = 0; q < 8; ++q) qc[q] = g_pack[qoff + b * Nq + qbase + q];
    const float4* cand = g_pack + coff + b * Ncand;

    uint4* h4 = (uint4*)sm.hist;
    uint4 z4 = make_uint4(0, 0, 0, 0);
    h4[tid] = z4; h4[tid + 512] = z4;
    if (tid < 8) { sm.n[tid] = 0; sm.nbn[tid] = 0; }
    if (tid == 16) sm.ln = 0;
    if (tid >= 32 && tid < 160) sm.cls[(tid - 32) >> 4][(tid - 32) & 15] = 0;
    __syncthreads();
#pragma unroll
    for (int i = 0; i < CPT; ++i) {
        int c = tid + i * 512;
        float4 p = cand[c];
        unsigned mb = 511u;
#pragma unroll
        for (int q = 0; q < 8; ++q) {
            if (selfex && c == qbase + q) continue;
            unsigned bin = __float_as_uint(fmaxf(dist2(qc[q], p), 0.f)) >> 22;
            atomicAdd(&sm.hist[(q << 9) + bin], 1u);
            mb = min(mb, bin);
        }
        sm.cbin[c] = (unsigned char)(mb >> 1);
    }
    __syncthreads();
    {
        int g = tid >> 6, t = tid & 63, wig = (tid >> 5) & 1;
        const unsigned* h = sm.hist + (g << 9);
        int base = t * 8, local = 0;
#pragma unroll
        for (int r = 0; r < 8; ++r) local += (int)h[base + r];
        int incl = local;
#pragma unroll
        for (int o = 1; o < 32; o <<= 1) {
            int tt = __shfl_up_sync(0xFFFFFFFFu, incl, o);
            if (lane >= o) incl += tt;
        }
        if (lane == 31) sm.wsum[g][wig] = incl;
        __syncthreads();
        int woff = wig ? sm.wsum[g][0] : 0;
        int excl = woff + incl - local;
        if (excl < k && k <= excl + local) {
            int c2 = excl, bin = base;
#pragma unroll
            for (int r = 0; r < 8; ++r) {
                int hh = (int)h[base + r];
                if (c2 + hh >= k) { bin = base + r; break; }
                c2 += hh;
            }
            sm.resbin[g] = bin; sm.resbelow[g] = c2;
        }
        __syncthreads();
    }
    unsigned rb[8]; unsigned rbmax = 0;
#pragma unroll
    for (int q = 0; q < 8; ++q) { rb[q] = (unsigned)sm.resbin[q]; rbmax = max(rbmax, rb[q]); }
    {
        unsigned char rbc = (unsigned char)(rbmax >> 1);
#pragma unroll
        for (int i = 0; i < CPT; ++i) {
            int c = tid + i * 512;
            if (sm.cbin[c] <= rbc) {
                unsigned p = atomicAdd(&sm.ln, 1u);
                if (p < 3072) sm.list[p] = (unsigned short)c;
            }
        }
    }
    __syncthreads();
    int Ln = (int)sm.ln;
    if (Ln <= 3072) {
        for (int j = tid; j < Ln; j += 512) {
            int c = (int)sm.list[j];
            float4 p = cand[c];
#pragma unroll
            for (int q = 0; q < 8; ++q) {
                if (selfex && c == qbase + q) continue;
                unsigned key = __float_as_uint(fmaxf(dist2(qc[q], p), 0.f));
                unsigned bin = key >> 22;
                if (bin < rb[q]) {
                    if (IS_LOSS) { unsigned pp = atomicAdd(&sm.nbn[q], 1u); sm.nb[q][pp] = c; }
                    else atomicAdd(&sm.cls[q][labels[b * NN + c]], 1u);
                } else if (bin == rb[q]) {
                    unsigned pp = atomicAdd(&sm.n[q], 1u);
                    if (pp < 128) { sm.skey[q][pp] = key; sm.sidx[q][pp] = c; }
                }
            }
        }
    } else {
        unsigned char rbc = (unsigned char)(rbmax >> 1);
#pragma unroll
        for (int i = 0; i < CPT; ++i) {
            int c = tid + i * 512;
            if (sm.cbin[c] > rbc) continue;
            float4 p = cand[c];
#pragma unroll
            for (int q = 0; q < 8; ++q) {
                if (selfex && c == qbase + q) continue;
                unsigned key = __float_as_uint(fmaxf(dist2(qc[q], p), 0.f));
                unsigned bin = key >> 22;
                if (bin < rb[q]) {
                    if (IS_LOSS) { unsigned pp = atomicAdd(&sm.nbn[q], 1u); sm.nb[q][pp] = c; }
                    else atomicAdd(&sm.cls[q][labels[b * NN + c]], 1u);
                } else if (bin == rb[q]) {
                    unsigned pp = atomicAdd(&sm.n[q], 1u);
                    if (pp < 128) { sm.skey[q][pp] = key; sm.sidx[q][pp] = c; }
                }
            }
        }
    }
    __syncthreads();
    {
        int g = tid >> 6, t = tid & 63;
        int n = (int)min(sm.n[g], 128u);
        int need = k - sm.resbelow[g];
        for (int j = t; j < n; j += 64) {
            unsigned kj = sm.skey[g][j]; int ij = sm.sidx[g][j], r = 0;
            for (int m = 0; m < n; ++m) {
                unsigned km = sm.skey[g][m];
                r += (km < kj) || (km == kj && sm.sidx[g][m] < ij);
            }
            if (r < need) {
                if (IS_LOSS) { unsigned pp = atomicAdd(&sm.nbn[g], 1u); sm.nb[g][pp] = ij; }
                else atomicAdd(&sm.cls[g][labels[b * NN + ij]], 1u);
            }
        }
    }
    __syncthreads();
    if (!IS_LOSS) {
        if ((tid & 63) == 0) {
            int g = tid >> 6;
            int best = 0; unsigned bc = sm.cls[g][0];
#pragma unroll
            for (int cc = 1; cc < 13; ++cc)
                if (sm.cls[g][cc] > bc) { bc = sm.cls[g][cc]; best = cc; }
            g_hard[qoff + b * Nq + qbase + g] = best;
        }
        return;
    }
    {
        int g = wid >> 1, w2 = wid & 1;
        int qi = qbase + g;
        int hb = qoff + b * Nq;
        int myh = g_hard[hb + qi];
        const float4* fq = (const float4*)(feat + (size_t)(b * Nq + qi) * D);
        int D4 = D >> 2;
        for (int j = w2; j < k; j += 2) {
            int nbi = sm.nb[g][j];
            const float4* fn = (const float4*)(feat + (size_t)(b * Nq + nbi) * D);
            float ss = 0.f;
            for (int d = lane; d < D4; d += 32) {
                float4 a = fq[d], z = fn[d];
                float dx = a.x - z.x, dy = a.y - z.y, dz = a.z - z.z, dw = a.w - z.w;
                ss += dx * dx + dy * dy + dz * dz + dw * dw;
            }
#pragma unroll
            for (int o = 16; o; o >>= 1) ss += __shfl_down_sync(0xFFFFFFFFu, ss, o);
            if (lane == 0) {
                sm.fd[g][j] = sqrtf(ss + 1e-6f);
                sm.msk[g][j] = (g_hard[hb + nbi] == myh) ? 1 : 0;
            }
        }
    }
    __syncthreads();
    if ((tid & 63) == 0) {
        int g = tid >> 6;
        float dmin = 3.0e38f; int cnt = 0;
        for (int j = 0; j < k; ++j) { dmin = fminf(dmin, sm.fd[g][j]); cnt += sm.msk[g][j]; }
        if (cnt > 0 && cnt < k) {
            float pos = 0.f, neg = 0.f;
            for (int j = 0; j < k; ++j) {
                float e = expf(dmin - sm.fd[g][j]);  // TEMPERATURE = 1
                neg += e;
                if (sm.msk[g][j]) pos += e;
            }
            atomicAdd(&g_bl_sum[stage], (double)(-logf(pos / neg + 1e-6f)));
            atomicAdd(&g_bl_cnt[stage], 1u);
        }
    }
}

// ---------------- kernel A: loss0 (pruned) + hard labels + CE ----------------
__global__ __launch_bounds__(512, 2) void kernelA(
        const float* __restrict__ f1, const int* __restrict__ labels,
        const float* __restrict__ lg0, const float* __restrict__ lg1,
        const float* __restrict__ lg2, const float* __restrict__ lg3,
        const float* __restrict__ lg4, const float* __restrict__ lg5,
        const int* __restrict__ i2, const int* __restrict__ i3,
        const int* __restrict__ i4, const int* __restrict__ i5) {
    __shared__ USmem u;
    int bx = blockIdx.x, b = blockIdx.y;
    if (bx < 1024) {
        loss0n_body(u.l, b, bx, f1);
    } else if (bx < 1280) {
        octo_body<16, false>(u.o, b, bx - 1024, 16384, 2048, 0, 8192, 4, 0, nullptr, 0, labels, false);
    } else if (bx < 1344) {
        octo_body<16, false>(u.o, b, bx - 1280, 20480, 512, 0, 8192, 16, 0, nullptr, 0, labels, false);
    } else if (bx < 1360) {
        octo_body<16, false>(u.o, b, bx - 1344, 21504, 128, 0, 8192, 64, 0, nullptr, 0, labels, false);
    } else if (bx < 1368) {
        quad_body<16>(u.q, b, bx - 1360, 21760, 32, 256, labels);
    } else {
        const int cum[7] = {0, 16384, 32768, 36864, 37888, 38144, 38208};
        int chunk = bx - 1368;
        int r = (chunk * 2 + b) * 512 + threadIdx.x;
        int job = 0;
        float l = 0.f;
        if (r < 38208) {
#pragma unroll
            for (int j = 1; j < 6; ++j) if (r >= cum[j]) job = j;
            const float* L[6] = {lg0, lg1, lg2, lg3, lg4, lg5};
            const int*   G[6] = {nullptr, nullptr, i2, i3, i4, i5};
            const int   lgn[6] = {13, 13, 11, 9, 7, 5};
            int lr = r - cum[job];
            int bb = lr >> lgn[job];
            const int* g = G[job];
            int lab = g ? labels[bb * NN + g[lr]] : labels[lr];
            const float* row = L[job] + (size_t)lr * 13;
            float v[13];
#pragma unroll
            for (int c = 0; c < 13; ++c) v[c] = row[c];
            float m = v[0];
#pragma unroll
            for (int c = 1; c < 13; ++c) m = fmaxf(m, v[c]);
            float s = 0.f;
#pragma unroll
            for (int c = 0; c < 13; ++c) s += expf(v[c] - m);
            l = (m + logf(s)) - v[lab];
        }
#pragma unroll
        for (int o = 16; o; o >>= 1) l += __shfl_down_sync(0xFFFFFFFFu, l, o);
        if ((threadIdx.x & 31) == 0 && l != 0.f) atomicAdd(&g_ce_sum[job], (double)l);
    }
}

// ---------------- kernel B: losses stages 1..4 (need g_hard) ----------------
__global__ __launch_bounds__(512, 2) void kernelB(
        const float* __restrict__ f2, const float* __restrict__ f3,
        const float* __restrict__ f4, const float* __restrict__ f5) {
    __shared__ USmem u;
    int bx = blockIdx.x, b = blockIdx.y;
    if (bx < 256) {
        octo_body<4, true>(u.o, b, bx, 16384, 2048, 16384, 2048, 23, 1, f2, 128, nullptr, true);
    } else if (bx < 320) {
        octo_body<1, true>(u.o, b, bx - 256, 20480, 512, 20480, 512, 23, 2, f3, 256, nullptr, true);
    } else {
        unsigned* s_key = u.o.hist;
        int*      s_nb  = u.o.nb[0];
        float*    s_fd  = u.o.fd[0];
        int*      s_msk = u.o.msk[0];
        int bi = bx - 320;
        int tid = threadIdx.x, lane = tid & 31, wid = tid >> 5;
        int stage, Ni, off, qi; const float* feat;
        if (bi < 128) { stage = 3; Ni = 128; off = 21504; feat = f4; qi = bi; }
        else          { stage = 4; Ni = 32;  off = 21760; feat = f5; qi = bi - 128; }
        const int D = 512, D4 = 128;
        float4 qc = g_pack[off + b * Ni + qi];
        unsigned myk = 0xFFFFFFFFu;
        if (tid < Ni && tid != qi) {
            float4 p = g_pack[off + b * Ni + tid];
            myk = __float_as_uint(fmaxf(dist2(qc, p), 0.f));
        }
        s_key[tid] = myk;
        __syncthreads();
        if (myk != 0xFFFFFFFFu) {
            int r = 0;
            for (int j = 0; j < Ni; ++j) {
                unsigned kj = s_key[j];
                r += (kj < myk) || (kj == myk && j < tid);
            }
            if (r < 23) s_nb[r] = tid;
        }
        __syncthreads();
        int myh = g_hard[off + b * Ni + qi];
        const float4* fq = (const float4*)(feat + (size_t)(b * Ni + qi) * D);
        for (int j = wid; j < 23; j += 16) {
            int nbi = s_nb[j];
            const float4* fn = (const float4*)(feat + (size_t)(b * Ni + nbi) * D);
            float ss = 0.f;
            for (int d = lane; d < D4; d += 32) {
                float4 a = fq[d], z = fn[d];
                float dx = a.x - z.x, dy = a.y - z.y, dz = a.z - z.z, dw = a.w - z.w;
                ss += dx * dx + dy * dy + dz * dz + dw * dw;
            }
#pragma unroll
            for (int o = 16; o; o >>= 1) ss += __shfl_down_sync(0xFFFFFFFFu, ss, o);
            if (lane == 0) {
                s_fd[j] = sqrtf(ss + 1e-6f);
                s_msk[j] = (g_hard[off + b * Ni + nbi] == myh) ? 1 : 0;
            }
        }
        __syncthreads();
        if (tid == 0) {
            float dmin = 3.0e38f; int cnt = 0;
            for (int j = 0; j < 23; ++j) { dmin = fminf(dmin, s_fd[j]); cnt += s_msk[j]; }
            if (cnt > 0 && cnt < 23) {
                float pos = 0.f, neg = 0.f;
                for (int j = 0; j < 23; ++j) {
                    float e = expf(dmin - s_fd[j]);
                    neg += e;
                    if (s_msk[j]) pos += e;
                }
                atomicAdd(&g_bl_sum[stage], (double)(-logf(pos / neg + 1e-6f)));
                atomicAdd(&g_bl_cnt[stage], 1u);
            }
        }
    }
}

// ---------------- finalize ----------------
__global__ void finalize_kernel(float* out) {
    const int ns[5] = {8192, 2048, 512, 128, 32};
    double ce = g_ce_sum[0] / (double)(BB * NN);
    double o = 0.0;
    for (int j = 0; j < 5; ++j) o += g_ce_sum[1 + j] / (double)(BB * ns[j]);
    double bl = 0.0;
    for (int i = 0; i < 5; ++i) {
        double dn = g_bl_cnt[i] > 0 ? (double)g_bl_cnt[i] : 1.0;
        bl += g_bl_sum[i] / dn;
    }
    out[0] = (float)(ce + 0.1 * bl + 0.1 * o);
}

// ---------------- launch ----------------
extern "C" void kernel_launch(void* const* d_in, const int* in_sizes, int n_in,
                              void* d_out, int out_size) {
    (void)in_sizes; (void)n_in; (void)out_size;
    // 0:labels, 1..4:index2..5, 5:output, per stage j: 6+3j:pred, 7+3j:xyz, 8+3j:feat
    const int* labels = (const int*)d_in[0];
    const int* idx2 = (const int*)d_in[1];
    const int* idx3 = (const int*)d_in[2];
    const int* idx4 = (const int*)d_in[3];
    const int* idx5 = (const int*)d_in[4];
    const float* output = (const float*)d_in[5];
    const float* pred[5], *xyz[5], *feat[5];
    for (int j = 0; j < 5; ++j) {
        pred[j] = (const float*)d_in[6 + 3 * j];
        xyz[j]  = (const float*)d_in[7 + 3 * j];
        feat[j] = (const float*)d_in[8 + 3 * j];
    }

    prep_kernel<<<86, 256>>>(xyz[0], xyz[1], xyz[2], xyz[3], xyz[4], labels);
    msort_kernel<<<BB, 512>>>();
    kernelA<<<dim3(1406, BB), 512>>>(feat[0], labels,
                                     output, pred[0], pred[1], pred[2], pred[3], pred[4],
                                     idx2, idx3, idx4, idx5);
    kernelB<<<dim3(480, BB), 512>>>(feat[1], feat[2], feat[3], feat[4]);

    finalize_kernel<<<1, 1>>>((float*)d_out);
}

// round 16
// speedup vs baseline: 1.0812x; 1.0812x over previous
#include <cuda_runtime.h>
#include <math.h>

#define BB 2
#define NN 8192

// Ns = {8192,2048,512,128,32}, D = {64,128,256,512,512}
// nsample-1 = {35,23,23,23,23}, kneighbors = {1,4,16,64,256}
// offsets into g_hard/g_pack: {0,16384,20480,21504,21760}

__device__ double   g_ce_sum[6];
__device__ double   g_bl_sum[5];
__device__ unsigned g_bl_cnt[5];
__device__ int      g_hard[21824];
__device__ float4   g_pack[21824];
__device__ float4   g_packQ[BB * NN];   // Morton-sorted stage-0 queries
__device__ int      g_qperm[BB * NN];

struct QSmem {                // quad: 4 queries x 1024 bins (k=256 hard path)
    unsigned hist[4096];
    int      wsum[4][4];
    int      resbin[4], resbelow[4];
    unsigned n[4];
    unsigned cls[4][16];
    unsigned skey[4][256];
    int      sidx[4][256];
};
struct OSmem {                // octo: 8 queries x 512 bins, min-bin sieve
    unsigned hist[4096];
    unsigned char  cbin[8192];
    unsigned short list[3072];
    unsigned ln;
    int      wsum[8][2];
    int      resbin[8], resbelow[8];
    unsigned n[8], nbn[8];
    unsigned cls[8][16];
    unsigned skey[8][128];
    int      sidx[8][128];
    int      nb[8][36];
    float    fd[8][36];
    int      msk[8][36];
};
struct LSmem {                // loss0: center-ball pruned, 8 sorted queries
    unsigned chist[512];
    union { unsigned char cbin[8192]; unsigned qhist[2048]; } u8;  // aliased
    unsigned short list[6144];
    unsigned char  sbin[6144];
    unsigned short list2[2048];
    unsigned ln, ln2;
    int      wsum[16];
    int      resbin[8], resbelow[8];
    unsigned n[8], nbn[8];
    int      qio[8];
    unsigned skey[8][128];
    int      sidx[8][128];
    int      nb[8][36];
    float    fd[8][36];
    int      msk[8][36];
};
union USmem { QSmem q; OSmem o; LSmem l; };

// ---------------- prep ----------------
__global__ void prep_kernel(const float* __restrict__ x1, const float* __restrict__ x2,
                            const float* __restrict__ x3, const float* __restrict__ x4,
                            const float* __restrict__ x5, const int* __restrict__ labels) {
    int id = blockIdx.x * blockDim.x + threadIdx.x;
    if (id < 6) g_ce_sum[id] = 0.0;
    if (id >= 8 && id < 13) { g_bl_sum[id - 8] = 0.0; g_bl_cnt[id - 8] = 0u; }
    if (id < BB * NN) g_hard[id] = labels[id];
    if (id < 21824) {
        const int offs[6] = {0, 16384, 20480, 21504, 21760, 21824};
        const float* xs[5] = {x1, x2, x3, x4, x5};
        int s = 0;
        while (id >= offs[s + 1]) ++s;
        int r = id - offs[s];
        const float* p = xs[s] + (size_t)r * 3;
        float x = p[0], y = p[1], z = p[2];
        g_pack[id] = make_float4(x, y, z, x * x + y * y + z * z);
    }
}

__device__ __forceinline__ unsigned part3(unsigned x) {
    x &= 1023u;
    x = (x | (x << 16)) & 0x030000FFu;
    x = (x | (x << 8))  & 0x0300F00Fu;
    x = (x | (x << 4))  & 0x030C30C3u;
    x = (x | (x << 2))  & 0x09249249u;
    return x;
}

// ---------------- Morton counting sort of stage-0 queries (one block per b) ----------------
__global__ __launch_bounds__(512) void msort_kernel() {
    __shared__ unsigned hist[4096];
    __shared__ unsigned short scode[8192];
    __shared__ int wsum[16];
    int b = blockIdx.x, tid = threadIdx.x, lane = tid & 31, wid = tid >> 5;
    for (int i = tid; i < 4096; i += 512) hist[i] = 0;
    __syncthreads();
#pragma unroll
    for (int j = 0; j < 16; ++j) {
        int id = tid + j * 512;
        float4 p = g_pack[b * NN + id];
        int cx = min(max((int)((p.x + 4.f) * 2.f), 0), 15);
        int cy = min(max((int)((p.y + 4.f) * 2.f), 0), 15);
        int cz = min(max((int)((p.z + 4.f) * 2.f), 0), 15);
        unsigned code = part3((unsigned)cx) | (part3((unsigned)cy) << 1) | (part3((unsigned)cz) << 2);
        scode[id] = (unsigned short)code;
        atomicAdd(&hist[code], 1u);
    }
    __syncthreads();
    int base = tid * 8, local = 0;
    int pre[8];
#pragma unroll
    for (int r = 0; r < 8; ++r) { pre[r] = local; local += (int)hist[base + r]; }
    int incl = local;
#pragma unroll
    for (int o = 1; o < 32; o <<= 1) {
        int t = __shfl_up_sync(0xFFFFFFFFu, incl, o);
        if (lane >= o) incl += t;
    }
    if (lane == 31) wsum[wid] = incl;
    __syncthreads();
    int woff = 0;
#pragma unroll
    for (int w = 0; w < 16; ++w) woff += (w < wid) ? wsum[w] : 0;
    int excl = woff + incl - local;
    __syncthreads();
#pragma unroll
    for (int r = 0; r < 8; ++r) hist[base + r] = (unsigned)(excl + pre[r]);
    __syncthreads();
#pragma unroll
    for (int j = 0; j < 16; ++j) {
        int id = tid + j * 512;
        unsigned code = scode[id];
        unsigned slot = atomicAdd(&hist[code], 1u);
        g_packQ[b * NN + slot] = g_pack[b * NN + id];
        g_qperm[b * NN + slot] = id;
    }
}

// pinned arithmetic: identical across passes
__device__ __forceinline__ float dist2(float4 q, float4 p) {
    float s = q.z * p.z;
    s = __fmaf_rn(q.y, p.y, s);
    s = __fmaf_rn(q.x, p.x, s);
    return __fmaf_rn(-2.f, s, q.w + p.w);
}

// ---------------- loss0: center-ball pruned body (8 sorted queries) ----------------
__device__ __forceinline__ void loss0n_body(LSmem& sm, int b, int blk,
                                            const float* __restrict__ feat) {
    int tid = threadIdx.x, lane = tid & 31, wid = tid >> 5;
    float4 qc[8];
    if (tid < 8) sm.qio[tid] = g_qperm[b * NN + blk * 8 + tid];
#pragma unroll
    for (int q = 0; q < 8; ++q) qc[q] = g_packQ[b * NN + blk * 8 + q];
    float cx = 0.f, cy = 0.f, cz = 0.f;
#pragma unroll
    for (int q = 0; q < 8; ++q) { cx += qc[q].x; cy += qc[q].y; cz += qc[q].z; }
    cx *= 0.125f; cy *= 0.125f; cz *= 0.125f;
    float4 cen = make_float4(cx, cy, cz, cx * cx + cy * cy + cz * cz);
    float R2 = 0.f;
#pragma unroll
    for (int q = 0; q < 8; ++q) R2 = fmaxf(R2, fmaxf(dist2(cen, qc[q]), 0.f));
    float R = sqrtf(R2);

    sm.chist[tid] = 0;
    if (tid == 0) { sm.ln = 0; sm.ln2 = 0; }
    if (tid < 8) { sm.n[tid] = 0; sm.nbn[tid] = 0; }
    __syncthreads();
    const float4* cand = g_pack + b * NN;

    // phase 1: ONE center distance + ONE atomic per candidate
#pragma unroll
    for (int i = 0; i < 16; ++i) {
        int c = tid + i * 512;
        float4 p = cand[c];
        unsigned key = __float_as_uint(fmaxf(dist2(cen, p), 0.f));
        atomicAdd(&sm.chist[(key >> 22) & 511u], 1u);
        int cb = (int)(key >> 20) - 960;
        sm.u8.cbin[c] = (unsigned char)min(max(cb, 0), 255);
    }
    __syncthreads();

    // scan center hist for rank 44 = 36 (k incl self) + 8 (block queries in candidate set)
    {
        int cnt = (int)sm.chist[tid];
        int incl = cnt;
#pragma unroll
        for (int o = 1; o < 32; o <<= 1) {
            int t = __shfl_up_sync(0xFFFFFFFFu, incl, o);
            if (lane >= o) incl += t;
        }
        if (lane == 31) sm.wsum[wid] = incl;
        __syncthreads();
        int woff = 0;
#pragma unroll
        for (int w = 0; w < 16; ++w) woff += (w < wid) ? sm.wsum[w] : 0;
        int excl = woff + incl - cnt;
        if (excl < 44 && 44 <= excl + cnt) sm.resbin[0] = tid;
        __syncthreads();
    }
    float t = __uint_as_float(((unsigned)sm.resbin[0] + 1u) << 22);  // bin upper edge
    float rr = sqrtf(t) + R + R;
    float cutd2 = rr * rr;
    int cut8 = min((int)(__float_as_uint(cutd2) >> 20) - 960 + 1, 255);

    // compact survivors
#pragma unroll
    for (int i = 0; i < 16; ++i) {
        int c = tid + i * 512;
        if ((int)sm.u8.cbin[c] <= cut8) {
            unsigned p = atomicAdd(&sm.ln, 1u);
            if (p < 6144) sm.list[p] = (unsigned short)c;
        }
    }
    __syncthreads();
    int Ln = (int)min(sm.ln, 6144u);
    bool ovf = sm.ln > 6144u;
    ((uint4*)sm.u8.qhist)[tid] = make_uint4(0, 0, 0, 0);
    __syncthreads();

    // phase 2: per-query octave histograms over survivors + per-survivor min-bin
    if (!ovf) {
        for (int j = tid; j < Ln; j += 512) {
            int c = (int)sm.list[j];
            float4 p = cand[c];
            unsigned mb = 255u;
#pragma unroll
            for (int q = 0; q < 8; ++q) {
                unsigned key = __float_as_uint(fmaxf(dist2(qc[q], p), 0.f));
                unsigned bin = (key >> 23) & 255u;
                atomicAdd(&sm.u8.qhist[(q << 8) + bin], 1u);
                mb = min(mb, bin);
            }
            sm.sbin[j] = (unsigned char)mb;
        }
    } else {
#pragma unroll
        for (int i = 0; i < 16; ++i) {
            int c = tid + i * 512;
            float4 p = cand[c];
            unsigned ck = __float_as_uint(fmaxf(dist2(cen, p), 0.f));
            if ((int)(ck >> 20) - 960 > cut8) continue;
#pragma unroll
            for (int q = 0; q < 8; ++q) {
                unsigned key = __float_as_uint(fmaxf(dist2(qc[q], p), 0.f));
                atomicAdd(&sm.u8.qhist[(q << 8) + ((key >> 23) & 255u)], 1u);
            }
        }
    }
    __syncthreads();

    // scan per-query hist for rank 36 (256 bins; 8 groups x 64 threads)
    {
        int g = tid >> 6, t2 = tid & 63, wig = (tid >> 5) & 1;
        int base = (g << 8) + t2 * 4, local = 0;
#pragma unroll
        for (int r = 0; r < 4; ++r) local += (int)sm.u8.qhist[base + r];
        int incl = local;
#pragma unroll
        for (int o = 1; o < 32; o <<= 1) {
            int tt = __shfl_up_sync(0xFFFFFFFFu, incl, o);
            if (lane >= o) incl += tt;
        }
        if (lane == 31) sm.wsum[g * 2 + wig] = incl;
        __syncthreads();
        int woff = wig ? sm.wsum[g * 2] : 0;
        int excl = woff + incl - local;
        if (excl < 36 && 36 <= excl + local) {
            int c2 = excl, bin = t2 * 4;
#pragma unroll
            for (int r = 0; r < 4; ++r) {
                int hh = (int)sm.u8.qhist[base + r];
                if (c2 + hh >= 36) { bin = t2 * 4 + r; break; }
                c2 += hh;
            }
            sm.resbin[g] = bin; sm.resbelow[g] = c2;
        }
        __syncthreads();
    }
    unsigned rb[8]; unsigned rbmax = 0;
#pragma unroll
    for (int q = 0; q < 8; ++q) { rb[q] = (unsigned)sm.resbin[q]; rbmax = max(rbmax, rb[q]); }

    // phase-3 COMPACTION (the R12 lesson: predicated skips don't pay in SIMT —
    // compact the near-survivors into list2, then do dense work)
    bool ovf2 = false;
    int L2 = 0;
    if (!ovf) {
        for (int j = tid; j < Ln; j += 512) {
            if ((unsigned)sm.sbin[j] <= rbmax) {
                unsigned p = atomicAdd(&sm.ln2, 1u);
                if (p < 2048) sm.list2[p] = sm.list[j];
            }
        }
        __syncthreads();
        L2 = (int)min(sm.ln2, 2048u);
        ovf2 = sm.ln2 > 2048u;
    }

    // phase 3: classify (dense over list2 when possible)
    if (!ovf && !ovf2) {
        for (int j = tid; j < L2; j += 512) {
            int c = (int)sm.list2[j];
            float4 p = cand[c];
#pragma unroll
            for (int q = 0; q < 8; ++q) {
                unsigned key = __float_as_uint(fmaxf(dist2(qc[q], p), 0.f));
                unsigned bin = (key >> 23) & 255u;
                if (bin < rb[q]) {
                    if (c != sm.qio[q]) {
                        unsigned pp = atomicAdd(&sm.nbn[q], 1u);
                        if (pp < 35) sm.nb[q][pp] = c;
                    }
                } else if (bin == rb[q]) {
                    unsigned pp = atomicAdd(&sm.n[q], 1u);
                    if (pp < 128) { sm.skey[q][pp] = key; sm.sidx[q][pp] = c; }
                }
            }
        }
    } else if (!ovf) {  // ovf2: sieved-predicated loop over full survivor list
        for (int j = tid; j < Ln; j += 512) {
            if ((unsigned)sm.sbin[j] > rbmax) continue;
            int c = (int)sm.list[j];
            float4 p = cand[c];
#pragma unroll
            for (int q = 0; q < 8; ++q) {
                unsigned key = __float_as_uint(fmaxf(dist2(qc[q], p), 0.f));
                unsigned bin = (key >> 23) & 255u;
                if (bin < rb[q]) {
                    if (c != sm.qio[q]) {
                        unsigned pp = atomicAdd(&sm.nbn[q], 1u);
                        if (pp < 35) sm.nb[q][pp] = c;
                    }
                } else if (bin == rb[q]) {
                    unsigned pp = atomicAdd(&sm.n[q], 1u);
                    if (pp < 128) { sm.skey[q][pp] = key; sm.sidx[q][pp] = c; }
                }
            }
        }
    } else {
#pragma unroll
        for (int i = 0; i < 16; ++i) {
            int c = tid + i * 512;
            float4 p = cand[c];
            unsigned ck = __float_as_uint(fmaxf(dist2(cen, p), 0.f));
            if ((int)(ck >> 20) - 960 > cut8) continue;
#pragma unroll
            for (int q = 0; q < 8; ++q) {
                unsigned key = __float_as_uint(fmaxf(dist2(qc[q], p), 0.f));
                unsigned bin = (key >> 23) & 255u;
                if (bin < rb[q]) {
                    if (c != sm.qio[q]) {
                        unsigned pp = atomicAdd(&sm.nbn[q], 1u);
                        if (pp < 35) sm.nb[q][pp] = c;
                    }
                } else if (bin == rb[q]) {
                    unsigned pp = atomicAdd(&sm.n[q], 1u);
                    if (pp < 128) { sm.skey[q][pp] = key; sm.sidx[q][pp] = c; }
                }
            }
        }
    }
    __syncthreads();

    // exact-rank the rank-bin survivors ((key,idx) lexicographic == top_k tie-break)
    {
        int g = tid >> 6, t2 = tid & 63;
        int n = (int)min(sm.n[g], 128u);
        int need = 36 - sm.resbelow[g];
        for (int j = t2; j < n; j += 64) {
            unsigned kj = sm.skey[g][j]; int ij = sm.sidx[g][j], r = 0;
            for (int m = 0; m < n; ++m) {
                unsigned km = sm.skey[g][m];
                r += (km < kj) || (km == kj && sm.sidx[g][m] < ij);
            }
            if (r < need && ij != sm.qio[g]) {
                unsigned pp = atomicAdd(&sm.nbn[g], 1u);
                if (pp < 35) sm.nb[g][pp] = ij;
            }
        }
    }
    __syncthreads();

    // feature distances (D=64): 2 warps per query
    {
        int g = wid >> 1, w2 = wid & 1;
        int qi = sm.qio[g];
        int myh = g_hard[b * NN + qi];
        const float4* fq = (const float4*)(feat + (size_t)(b * NN + qi) * 64);
        for (int j = w2; j < 35; j += 2) {
            int nbi = sm.nb[g][j];
            const float4* fn = (const float4*)(feat + (size_t)(b * NN + nbi) * 64);
            float ss = 0.f;
            if (lane < 16) {
                float4 a = fq[lane], z = fn[lane];
                float dx = a.x - z.x, dy = a.y - z.y, dz = a.z - z.z, dw = a.w - z.w;
                ss = dx * dx + dy * dy + dz * dz + dw * dw;
            }
#pragma unroll
            for (int o = 16; o; o >>= 1) ss += __shfl_down_sync(0xFFFFFFFFu, ss, o);
            if (lane == 0) {
                sm.fd[g][j] = sqrtf(ss + 1e-6f);
                sm.msk[g][j] = (g_hard[b * NN + nbi] == myh) ? 1 : 0;
            }
        }
    }
    __syncthreads();
    if ((tid & 63) == 0) {
        int g = tid >> 6;
        float dmin = 3.0e38f; int cnt = 0;
        for (int j = 0; j < 35; ++j) { dmin = fminf(dmin, sm.fd[g][j]); cnt += sm.msk[g][j]; }
        if (cnt > 0 && cnt < 35) {
            float pos = 0.f, neg = 0.f;
            for (int j = 0; j < 35; ++j) {
                float e = expf(dmin - sm.fd[g][j]);  // TEMPERATURE = 1
                neg += e;
                if (sm.msk[g][j]) pos += e;
            }
            atomicAdd(&g_bl_sum[0], (double)(-logf(pos / neg + 1e-6f)));
            atomicAdd(&g_bl_cnt[0], 1u);
        }
    }
}

// ---------------- quad body: 4 queries, 1024 bins (k=256 hard path) ----------------
template <int CPT>
__device__ __forceinline__ void quad_body(
        QSmem& sm, int b, int quad, int qoff, int Nq, int k,
        const int* __restrict__ labels) {
    int tid = threadIdx.x, lane = tid & 31;
    int qbase = quad * 4;
    float4 qc[4];
#pragma unroll
    for (int q = 0; q < 4; ++q) qc[q] = g_pack[qoff + b * Nq + qbase + q];
    const float4* cand = g_pack + b * NN;

    uint4* h4 = (uint4*)sm.hist;
    uint4 z4 = make_uint4(0, 0, 0, 0);
    h4[tid] = z4; h4[tid + 512] = z4;
    if (tid < 4) sm.n[tid] = 0;
    if (tid >= 32 && tid < 96) sm.cls[(tid - 32) >> 4][(tid - 32) & 15] = 0;
    __syncthreads();
#pragma unroll
    for (int i = 0; i < CPT; ++i) {
        int c = tid + i * 512;
        float4 p = cand[c];
#pragma unroll
        for (int q = 0; q < 4; ++q) {
            unsigned bin = __float_as_uint(fmaxf(dist2(qc[q], p), 0.f)) >> 21;
            atomicAdd(&sm.hist[(q << 10) + bin], 1u);
        }
    }
    __syncthreads();
    {
        int g = tid >> 7, t = tid & 127, wig = (tid >> 5) & 3;
        const unsigned* h = sm.hist + (g << 10);
        int base = t * 8, local = 0;
#pragma unroll
        for (int r = 0; r < 8; ++r) local += (int)h[base + r];
        int incl = local;
#pragma unroll
        for (int o = 1; o < 32; o <<= 1) {
            int tt = __shfl_up_sync(0xFFFFFFFFu, incl, o);
            if (lane >= o) incl += tt;
        }
        if (lane == 31) sm.wsum[g][wig] = incl;
        __syncthreads();
        int woff = 0;
#pragma unroll
        for (int w = 0; w < 4; ++w) woff += (w < wig) ? sm.wsum[g][w] : 0;
        int excl = woff + incl - local;
        if (excl < k && k <= excl + local) {
            int c2 = excl, bin = base;
#pragma unroll
            for (int r = 0; r < 8; ++r) {
                int hh = (int)h[base + r];
                if (c2 + hh >= k) { bin = base + r; break; }
                c2 += hh;
            }
            sm.resbin[g] = bin; sm.resbelow[g] = c2;
        }
        __syncthreads();
    }
    unsigned rb[4];
#pragma unroll
    for (int q = 0; q < 4; ++q) rb[q] = (unsigned)sm.resbin[q];
#pragma unroll
    for (int i = 0; i < CPT; ++i) {
        int c = tid + i * 512;
        float4 p = cand[c];
#pragma unroll
        for (int q = 0; q < 4; ++q) {
            unsigned key = __float_as_uint(fmaxf(dist2(qc[q], p), 0.f));
            unsigned bin = key >> 21;
            if (bin < rb[q]) {
                atomicAdd(&sm.cls[q][labels[b * NN + c]], 1u);
            } else if (bin == rb[q]) {
                unsigned pp = atomicAdd(&sm.n[q], 1u);
                if (pp < 256) { sm.skey[q][pp] = key; sm.sidx[q][pp] = c; }
            }
        }
    }
    __syncthreads();
    {
        int g = tid >> 7, t = tid & 127;
        int n = (int)min(sm.n[g], 256u);
        int need = k - sm.resbelow[g];
        for (int j = t; j < n; j += 128) {
            unsigned kj = sm.skey[g][j]; int ij = sm.sidx[g][j], r = 0;
            for (int m = 0; m < n; ++m) {
                unsigned km = sm.skey[g][m];
                r += (km < kj) || (km == kj && sm.sidx[g][m] < ij);
            }
            if (r < need) atomicAdd(&sm.cls[g][labels[b * NN + ij]], 1u);
        }
    }
    __syncthreads();
    if ((tid & 127) == 0) {
        int g = tid >> 7;
        int best = 0; unsigned bc = sm.cls[g][0];
#pragma unroll
        for (int cc = 1; cc < 13; ++cc)
            if (sm.cls[g][cc] > bc) { bc = sm.cls[g][cc]; best = cc; }
        g_hard[qoff + b * Nq + qbase + g] = best;
    }
}

// ---------------- octo body: 8 queries, 512 bins, min-bin sieve ----------------
template <int CPT, bool IS_LOSS>
__device__ __forceinline__ void octo_body(
        OSmem& sm, int b, int oct, int qoff, int Nq, int coff, int Ncand,
        int k, int stage, const float* __restrict__ feat, int D,
        const int* __restrict__ labels, bool selfex) {
    int tid = threadIdx.x, lane = tid & 31, wid = tid >> 5;
    int qbase = oct * 8;
    float4 qc[8];
#pragma unroll
    for (int q = 0; q < 8; ++q) qc[q] = g_pack[qoff + b * Nq + qbase + q];
    const float4* cand = g_pack + coff + b * Ncand;

    uint4* h4 = (uint4*)sm.hist;
    uint4 z4 = make_uint4(0, 0, 0, 0);
    h4[tid] = z4; h4[tid + 512] = z4;
    if (tid < 8) { sm.n[tid] = 0; sm.nbn[tid] = 0; }
    if (tid == 16) sm.ln = 0;
    if (tid >= 32 && tid < 160) sm.cls[(tid - 32) >> 4][(tid - 32) & 15] = 0;
    __syncthreads();
#pragma unroll
    for (int i = 0; i < CPT; ++i) {
        int c = tid + i * 512;
        float4 p = cand[c];
        unsigned mb = 511u;
#pragma unroll
        for (int q = 0; q < 8; ++q) {
            if (selfex && c == qbase + q) continue;
            unsigned bin = __float_as_uint(fmaxf(dist2(qc[q], p), 0.f)) >> 22;
            atomicAdd(&sm.hist[(q << 9) + bin], 1u);
            mb = min(mb, bin);
        }
        sm.cbin[c] = (unsigned char)(mb >> 1);
    }
    __syncthreads();
    {
        int g = tid >> 6, t = tid & 63, wig = (tid >> 5) & 1;
        const unsigned* h = sm.hist + (g << 9);
        int base = t * 8, local = 0;
#pragma unroll
        for (int r = 0; r < 8; ++r) local += (int)h[base + r];
        int incl = local;
#pragma unroll
        for (int o = 1; o < 32; o <<= 1) {
            int tt = __shfl_up_sync(0xFFFFFFFFu, incl, o);
            if (lane >= o) incl += tt;
        }
        if (lane == 31) sm.wsum[g][wig] = incl;
        __syncthreads();
        int woff = wig ? sm.wsum[g][0] : 0;
        int excl = woff + incl - local;
        if (excl < k && k <= excl + local) {
            int c2 = excl, bin = base;
#pragma unroll
            for (int r = 0; r < 8; ++r) {
                int hh = (int)h[base + r];
                if (c2 + hh >= k) { bin = base + r; break; }
                c2 += hh;
            }
            sm.resbin[g] = bin; sm.resbelow[g] = c2;
        }
        __syncthreads();
    }
    unsigned rb[8]; unsigned rbmax = 0;
#pragma unroll
    for (int q = 0; q < 8; ++q) { rb[q] = (unsigned)sm.resbin[q]; rbmax = max(rbmax, rb[q]); }
    {
        unsigned char rbc = (unsigned char)(rbmax >> 1);
#pragma unroll
        for (int i = 0; i < CPT; ++i) {
            int c = tid + i * 512;
            if (sm.cbin[c] <= rbc) {
                unsigned p = atomicAdd(&sm.ln, 1u);
                if (p < 3072) sm.list[p] = (unsigned short)c;
            }
        }
    }
    __syncthreads();
    int Ln = (int)sm.ln;
    if (Ln <= 3072) {
        for (int j = tid; j < Ln; j += 512) {
            int c = (int)sm.list[j];
            float4 p = cand[c];
#pragma unroll
            for (int q = 0; q < 8; ++q) {
                if (selfex && c == qbase + q) continue;
                unsigned key = __float_as_uint(fmaxf(dist2(qc[q], p), 0.f));
                unsigned bin = key >> 22;
                if (bin < rb[q]) {
                    if (IS_LOSS) { unsigned pp = atomicAdd(&sm.nbn[q], 1u); sm.nb[q][pp] = c; }
                    else atomicAdd(&sm.cls[q][labels[b * NN + c]], 1u);
                } else if (bin == rb[q]) {
                    unsigned pp = atomicAdd(&sm.n[q], 1u);
                    if (pp < 128) { sm.skey[q][pp] = key; sm.sidx[q][pp] = c; }
                }
            }
        }
    } else {
        unsigned char rbc = (unsigned char)(rbmax >> 1);
#pragma unroll
        for (int i = 0; i < CPT; ++i) {
            int c = tid + i * 512;
            if (sm.cbin[c] > rbc) continue;
            float4 p = cand[c];
#pragma unroll
            for (int q = 0; q < 8; ++q) {
                if (selfex && c == qbase + q) continue;
                unsigned key = __float_as_uint(fmaxf(dist2(qc[q], p), 0.f));
                unsigned bin = key >> 22;
                if (bin < rb[q]) {
                    if (IS_LOSS) { unsigned pp = atomicAdd(&sm.nbn[q], 1u); sm.nb[q][pp] = c; }
                    else atomicAdd(&sm.cls[q][labels[b * NN + c]], 1u);
                } else if (bin == rb[q]) {
                    unsigned pp = atomicAdd(&sm.n[q], 1u);
                    if (pp < 128) { sm.skey[q][pp] = key; sm.sidx[q][pp] = c; }
                }
            }
        }
    }
    __syncthreads();
    {
        int g = tid >> 6, t = tid & 63;
        int n = (int)min(sm.n[g], 128u);
        int need = k - sm.resbelow[g];
        for (int j = t; j < n; j += 64) {
            unsigned kj = sm.skey[g][j]; int ij = sm.sidx[g][j], r = 0;
            for (int m = 0; m < n; ++m) {
                unsigned km = sm.skey[g][m];
                r += (km < kj) || (km == kj && sm.sidx[g][m] < ij);
            }
            if (r < need) {
                if (IS_LOSS) { unsigned pp = atomicAdd(&sm.nbn[g], 1u); sm.nb[g][pp] = ij; }
                else atomicAdd(&sm.cls[g][labels[b * NN + ij]], 1u);
            }
        }
    }
    __syncthreads();
    if (!IS_LOSS) {
        if ((tid & 63) == 0) {
            int g = tid >> 6;
            int best = 0; unsigned bc = sm.cls[g][0];
#pragma unroll
            for (int cc = 1; cc < 13; ++cc)
                if (sm.cls[g][cc] > bc) { bc = sm.cls[g][cc]; best = cc; }
            g_hard[qoff + b * Nq + qbase + g] = best;
        }
        return;
    }
    {
        int g = wid >> 1, w2 = wid & 1;
        int qi = qbase + g;
        int hb = qoff + b * Nq;
        int myh = g_hard[hb + qi];
        const float4* fq = (const float4*)(feat + (size_t)(b * Nq + qi) * D);
        int D4 = D >> 2;
        for (int j = w2; j < k; j += 2) {
            int nbi = sm.nb[g][j];
            const float4* fn = (const float4*)(feat + (size_t)(b * Nq + nbi) * D);
            float ss = 0.f;
            for (int d = lane; d < D4; d += 32) {
                float4 a = fq[d], z = fn[d];
                float dx = a.x - z.x, dy = a.y - z.y, dz = a.z - z.z, dw = a.w - z.w;
                ss += dx * dx + dy * dy + dz * dz + dw * dw;
            }
#pragma unroll
            for (int o = 16; o; o >>= 1) ss += __shfl_down_sync(0xFFFFFFFFu, ss, o);
            if (lane == 0) {
                sm.fd[g][j] = sqrtf(ss + 1e-6f);
                sm.msk[g][j] = (g_hard[hb + nbi] == myh) ? 1 : 0;
            }
        }
    }
    __syncthreads();
    if ((tid & 63) == 0) {
        int g = tid >> 6;
        float dmin = 3.0e38f; int cnt = 0;
        for (int j = 0; j < k; ++j) { dmin = fminf(dmin, sm.fd[g][j]); cnt += sm.msk[g][j]; }
        if (cnt > 0 && cnt < k) {
            float pos = 0.f, neg = 0.f;
            for (int j = 0; j < k; ++j) {
                float e = expf(dmin - sm.fd[g][j]);  // TEMPERATURE = 1
                neg += e;
                if (sm.msk[g][j]) pos += e;
            }
            atomicAdd(&g_bl_sum[stage], (double)(-logf(pos / neg + 1e-6f)));
            atomicAdd(&g_bl_cnt[stage], 1u);
        }
    }
}

// ---------------- kernel A: loss0 (pruned) + hard labels + CE ----------------
__global__ __launch_bounds__(512, 2) void kernelA(
        const float* __restrict__ f1, const int* __restrict__ labels,
        const float* __restrict__ lg0, const float* __restrict__ lg1,
        const float* __restrict__ lg2, const float* __restrict__ lg3,
        const float* __restrict__ lg4, const float* __restrict__ lg5,
        const int* __restrict__ i2, const int* __restrict__ i3,
        const int* __restrict__ i4, const int* __restrict__ i5) {
    __shared__ USmem u;
    int bx = blockIdx.x, b = blockIdx.y;
    if (bx < 1024) {
        loss0n_body(u.l, b, bx, f1);
    } else if (bx < 1280) {
        octo_body<16, false>(u.o, b, bx - 1024, 16384, 2048, 0, 8192, 4, 0, nullptr, 0, labels, false);
    } else if (bx < 1344) {
        octo_body<16, false>(u.o, b, bx - 1280, 20480, 512, 0, 8192, 16, 0, nullptr, 0, labels, false);
    } else if (bx < 1360) {
        octo_body<16, false>(u.o, b, bx - 1344, 21504, 128, 0, 8192, 64, 0, nullptr, 0, labels, false);
    } else if (bx < 1368) {
        quad_body<16>(u.q, b, bx - 1360, 21760, 32, 256, labels);
    } else {
        const int cum[7] = {0, 16384, 32768, 36864, 37888, 38144, 38208};
        int chunk = bx - 1368;
        int r = (chunk * 2 + b) * 512 + threadIdx.x;
        int job = 0;
        float l = 0.f;
        if (r < 38208) {
#pragma unroll
            for (int j = 1; j < 6; ++j) if (r >= cum[j]) job = j;
            const float* L[6] = {lg0, lg1, lg2, lg3, lg4, lg5};
            const int*   G[6] = {nullptr, nullptr, i2, i3, i4, i5};
            const int   lgn[6] = {13, 13, 11, 9, 7, 5};
            int lr = r - cum[job];
            int bb = lr >> lgn[job];
            const int* g = G[job];
            int lab = g ? labels[bb * NN + g[lr]] : labels[lr];
            const float* row = L[job] + (size_t)lr * 13;
            float v[13];
#pragma unroll
            for (int c = 0; c < 13; ++c) v[c] = row[c];
            float m = v[0];
#pragma unroll
            for (int c = 1; c < 13; ++c) m = fmaxf(m, v[c]);
            float s = 0.f;
#pragma unroll
            for (int c = 0; c < 13; ++c) s += expf(v[c] - m);
            l = (m + logf(s)) - v[lab];
        }
#pragma unroll
        for (int o = 16; o; o >>= 1) l += __shfl_down_sync(0xFFFFFFFFu, l, o);
        if ((threadIdx.x & 31) == 0 && l != 0.f) atomicAdd(&g_ce_sum[job], (double)l);
    }
}

// ---------------- kernel B: losses stages 1..4 (need g_hard) ----------------
__global__ __launch_bounds__(512, 2) void kernelB(
        const float* __restrict__ f2, const float* __restrict__ f3,
        const float* __restrict__ f4, const float* __restrict__ f5) {
    __shared__ USmem u;
    int bx = blockIdx.x, b = blockIdx.y;
    if (bx < 256) {
        octo_body<4, true>(u.o, b, bx, 16384, 2048, 16384, 2048, 23, 1, f2, 128, nullptr, true);
    } else if (bx < 320) {
        octo_body<1, true>(u.o, b, bx - 256, 20480, 512, 20480, 512, 23, 2, f3, 256, nullptr, true);
    } else {
        unsigned* s_key = u.o.hist;
        int*      s_nb  = u.o.nb[0];
        float*    s_fd  = u.o.fd[0];
        int*      s_msk = u.o.msk[0];
        int bi = bx - 320;
        int tid = threadIdx.x, lane = tid & 31, wid = tid >> 5;
        int stage, Ni, off, qi; const float* feat;
        if (bi < 128) { stage = 3; Ni = 128; off = 21504; feat = f4; qi = bi; }
        else          { stage = 4; Ni = 32;  off = 21760; feat = f5; qi = bi - 128; }
        const int D = 512, D4 = 128;
        float4 qc = g_pack[off + b * Ni + qi];
        unsigned myk = 0xFFFFFFFFu;
        if (tid < Ni && tid != qi) {
            float4 p = g_pack[off + b * Ni + tid];
            myk = __float_as_uint(fmaxf(dist2(qc, p), 0.f));
        }
        s_key[tid] = myk;
        __syncthreads();
        if (myk != 0xFFFFFFFFu) {
            int r = 0;
            for (int j = 0; j < Ni; ++j) {
                unsigned kj = s_key[j];
                r += (kj < myk) || (kj == myk && j < tid);
            }
            if (r < 23) s_nb[r] = tid;
        }
        __syncthreads();
        int myh = g_hard[off + b * Ni + qi];
        const float4* fq = (const float4*)(feat + (size_t)(b * Ni + qi) * D);
        for (int j = wid; j < 23; j += 16) {
            int nbi = s_nb[j];
            const float4* fn = (const float4*)(feat + (size_t)(b * Ni + nbi) * D);
            float ss = 0.f;
            for (int d = lane; d < D4; d += 32) {
                float4 a = fq[d], z = fn[d];
                float dx = a.x - z.x, dy = a.y - z.y, dz = a.z - z.z, dw = a.w - z.w;
                ss += dx * dx + dy * dy + dz * dz + dw * dw;
            }
#pragma unroll
            for (int o = 16; o; o >>= 1) ss += __shfl_down_sync(0xFFFFFFFFu, ss, o);
            if (lane == 0) {
                s_fd[j] = sqrtf(ss + 1e-6f);
                s_msk[j] = (g_hard[off + b * Ni + nbi] == myh) ? 1 : 0;
            }
        }
        __syncthreads();
        if (tid == 0) {
            float dmin = 3.0e38f; int cnt = 0;
            for (int j = 0; j < 23; ++j) { dmin = fminf(dmin, s_fd[j]); cnt += s_msk[j]; }
            if (cnt > 0 && cnt < 23) {
                float pos = 0.f, neg = 0.f;
                for (int j = 0; j < 23; ++j) {
                    float e = expf(dmin - s_fd[j]);
                    neg += e;
                    if (s_msk[j]) pos += e;
                }
                atomicAdd(&g_bl_sum[stage], (double)(-logf(pos / neg + 1e-6f)));
                atomicAdd(&g_bl_cnt[stage], 1u);
            }
        }
    }
}

// ---------------- finalize ----------------
__global__ void finalize_kernel(float* out) {
    const int ns[5] = {8192, 2048, 512, 128, 32};
    double ce = g_ce_sum[0] / (double)(BB * NN);
    double o = 0.0;
    for (int j = 0; j < 5; ++j) o += g_ce_sum[1 + j] / (double)(BB * ns[j]);
    double bl = 0.0;
    for (int i = 0; i < 5; ++i) {
        double dn = g_bl_cnt[i] > 0 ? (double)g_bl_cnt[i] : 1.0;
        bl += g_bl_sum[i] / dn;
    }
    out[0] = (float)(ce + 0.1 * bl + 0.1 * o);
}

// ---------------- launch ----------------
extern "C" void kernel_launch(void* const* d_in, const int* in_sizes, int n_in,
                              void* d_out, int out_size) {
    (void)in_sizes; (void)n_in; (void)out_size;
    // 0:labels, 1..4:index2..5, 5:output, per stage j: 6+3j:pred, 7+3j:xyz, 8+3j:feat
    const int* labels = (const int*)d_in[0];
    const int* idx2 = (const int*)d_in[1];
    const int* idx3 = (const int*)d_in[2];
    const int* idx4 = (const int*)d_in[3];
    const int* idx5 = (const int*)d_in[4];
    const float* output = (const float*)d_in[5];
    const float* pred[5], *xyz[5], *feat[5];
    for (int j = 0; j < 5; ++j) {
        pred[j] = (const float*)d_in[6 + 3 * j];
        xyz[j]  = (const float*)d_in[7 + 3 * j];
        feat[j] = (const float*)d_in[8 + 3 * j];
    }

    prep_kernel<<<86, 256>>>(xyz[0], xyz[1], xyz[2], xyz[3], xyz[4], labels);
    msort_kernel<<<BB, 512>>>();
    kernelA<<<dim3(1406, BB), 512>>>(feat[0], labels,
                                     output, pred[0], pred[1], pred[2], pred[3], pred[4],
                                     idx2, idx3, idx4, idx5);
    kernelB<<<dim3(480, BB), 512>>>(feat[1], feat[2], feat[3], feat[4]);

    finalize_kernel<<<1, 1>>>((float*)d_out);
}